// round 1
// baseline (speedup 1.0000x reference)
#include <cuda_runtime.h>
#include <cuda_bf16.h>

// Problem constants
#define B_  8
#define C_  128
#define H_  64
#define W_  64
#define HW_ (H_ * W_)
#define KS  7
#define PAD 3
#define NP  (KS * KS)   // 49 neighborhood offsets

// Scratch for q, k, v in (B, C, H, W) layout — device globals (no allocation allowed)
__device__ float g_q[B_ * C_ * HW_];
__device__ float g_k[B_ * C_ * HW_];
__device__ float g_v[B_ * C_ * HW_];

// ---------------------------------------------------------------------------
// Kernel 1: q/k/v = W @ x + b  (per-batch GEMM: M=128 oc, N=64-px tile, K=128)
// grid = (B*HW/64, 3), block = 256 threads
// thread tile: 8 out-channels x 4 pixels
// ---------------------------------------------------------------------------
__global__ __launch_bounds__(256) void qkv_gemm(
    const float* __restrict__ x,
    const float* __restrict__ Wq, const float* __restrict__ bq,
    const float* __restrict__ Wk, const float* __restrict__ bk,
    const float* __restrict__ Wv, const float* __restrict__ bv)
{
    __shared__ __align__(16) float Wt[16][132];   // W^T chunk: [k][o], padded
    __shared__ __align__(16) float Xs[16][64];    // x chunk:   [k][p]

    const float* Wm;
    const float* bias;
    float* out;
    if (blockIdx.y == 0)      { Wm = Wq; bias = bq; out = g_q; }
    else if (blockIdx.y == 1) { Wm = Wk; bias = bk; out = g_k; }
    else                      { Wm = Wv; bias = bv; out = g_v; }

    const int t   = blockIdx.x;
    const int b   = t >> 6;           // 64 pixel-tiles per batch image
    const int hw0 = (t & 63) << 6;    // 64 pixels per tile
    const float* xb = x + (size_t)b * C_ * HW_;

    const int pg = threadIdx.x & 15;   // pixel group
    const int og = threadIdx.x >> 4;   // out-channel group
    const int p0 = pg * 4;
    const int o0 = og * 8;

    float acc[8][4];
#pragma unroll
    for (int i = 0; i < 8; ++i)
#pragma unroll
        for (int j = 0; j < 4; ++j) acc[i][j] = 0.f;

    for (int kk = 0; kk < C_; kk += 16) {
        __syncthreads();
        // load W chunk (2048 floats), store transposed
#pragma unroll
        for (int r = 0; r < 8; ++r) {
            int i  = threadIdx.x + 256 * r;
            int cl = i & 15;
            int o  = i >> 4;
            Wt[cl][o] = Wm[o * C_ + kk + cl];
        }
        // load X chunk (1024 floats)
#pragma unroll
        for (int r = 0; r < 4; ++r) {
            int i  = threadIdx.x + 256 * r;
            int pp = i & 63;
            int kl = i >> 6;
            Xs[kl][pp] = xb[(size_t)(kk + kl) * HW_ + hw0 + pp];
        }
        __syncthreads();

#pragma unroll
        for (int k = 0; k < 16; ++k) {
            float4 w0 = *(const float4*)&Wt[k][o0];
            float4 w1 = *(const float4*)&Wt[k][o0 + 4];
            float4 xv = *(const float4*)&Xs[k][p0];
            float wv[8] = {w0.x, w0.y, w0.z, w0.w, w1.x, w1.y, w1.z, w1.w};
            float xs4[4] = {xv.x, xv.y, xv.z, xv.w};
#pragma unroll
            for (int i = 0; i < 8; ++i)
#pragma unroll
                for (int j = 0; j < 4; ++j)
                    acc[i][j] += wv[i] * xs4[j];
        }
    }

    // epilogue: add bias, write (B, C, HW)
#pragma unroll
    for (int i = 0; i < 8; ++i) {
        float bv_ = bias[o0 + i];
        float4 r;
        r.x = acc[i][0] + bv_;
        r.y = acc[i][1] + bv_;
        r.z = acc[i][2] + bv_;
        r.w = acc[i][3] + bv_;
        *(float4*)&out[((size_t)b * C_ + o0 + i) * HW_ + hw0 + p0] = r;
    }
}

// ---------------------------------------------------------------------------
// Kernel 2: local attention.
// Tile: 16x8 pixels, 128 threads (1 px/thread). Channels streamed 4 at a time
// (float4), k/v halo (22x14) staged in shared memory. 49 logits in registers.
// grid = (W/16, H/8, B), block = 128
// ---------------------------------------------------------------------------
#define TW 16
#define TH 8
#define HXW (TW + 6)
#define HXH (TH + 6)

__global__ __launch_bounds__(128) void local_attn(float* __restrict__ out)
{
    __shared__ __align__(16) float4 s_tile[HXH][HXW];  // one 4-channel halo chunk

    const int tx = threadIdx.x & (TW - 1);
    const int ty = threadIdx.x / TW;
    const int x0 = blockIdx.x * TW;
    const int y0 = blockIdx.y * TH;
    const int b  = blockIdx.z;
    const int gx = x0 + tx;
    const int gy = y0 + ty;

    const float* qb = g_q + (size_t)b * C_ * HW_;
    const float* kb = g_k + (size_t)b * C_ * HW_;
    const float* vb = g_v + (size_t)b * C_ * HW_;

    float logits[NP];
#pragma unroll
    for (int p = 0; p < NP; ++p) logits[p] = 0.f;

    // ---- Pass 1: logits += q . k(neighbor), channel chunks of 4 ----
    for (int c0 = 0; c0 < C_; c0 += 4) {
        __syncthreads();   // protect previous chunk's reads
        for (int i = threadIdx.x; i < HXH * HXW; i += blockDim.x) {
            int hy = i / HXW, hx = i - hy * HXW;
            int sy = y0 + hy - PAD, sx = x0 + hx - PAD;
            float4 val = make_float4(0.f, 0.f, 0.f, 0.f);
            if (sy >= 0 && sy < H_ && sx >= 0 && sx < W_) {
                const float* p = kb + (size_t)c0 * HW_ + sy * W_ + sx;
                val.x = p[0];
                val.y = p[HW_];
                val.z = p[2 * HW_];
                val.w = p[3 * HW_];
            }
            s_tile[hy][hx] = val;
        }
        __syncthreads();

        const float* qp = qb + (size_t)c0 * HW_ + gy * W_ + gx;
        float4 qf = make_float4(qp[0], qp[HW_], qp[2 * HW_], qp[3 * HW_]);

#pragma unroll
        for (int p = 0; p < NP; ++p) {
            const int dy = p / KS, dx = p - dy * KS;
            float4 kv = s_tile[ty + dy][tx + dx];
            logits[p] += qf.x * kv.x + qf.y * kv.y + qf.z * kv.z + qf.w * kv.w;
        }
    }

    // ---- softmax over 49 offsets (in registers) ----
    float m = logits[0];
#pragma unroll
    for (int p = 1; p < NP; ++p) m = fmaxf(m, logits[p]);
    float s = 0.f;
#pragma unroll
    for (int p = 0; p < NP; ++p) {
        logits[p] = __expf(logits[p] - m);
        s += logits[p];
    }
    const float inv = 1.f / s;
#pragma unroll
    for (int p = 0; p < NP; ++p) logits[p] *= inv;

    // ---- Pass 2: y = sum_p attn[p] * v(neighbor) ----
    for (int c0 = 0; c0 < C_; c0 += 4) {
        __syncthreads();
        for (int i = threadIdx.x; i < HXH * HXW; i += blockDim.x) {
            int hy = i / HXW, hx = i - hy * HXW;
            int sy = y0 + hy - PAD, sx = x0 + hx - PAD;
            float4 val = make_float4(0.f, 0.f, 0.f, 0.f);
            if (sy >= 0 && sy < H_ && sx >= 0 && sx < W_) {
                const float* p = vb + (size_t)c0 * HW_ + sy * W_ + sx;
                val.x = p[0];
                val.y = p[HW_];
                val.z = p[2 * HW_];
                val.w = p[3 * HW_];
            }
            s_tile[hy][hx] = val;
        }
        __syncthreads();

        float4 accv = make_float4(0.f, 0.f, 0.f, 0.f);
#pragma unroll
        for (int p = 0; p < NP; ++p) {
            const int dy = p / KS, dx = p - dy * KS;
            float4 vv = s_tile[ty + dy][tx + dx];
            accv.x += logits[p] * vv.x;
            accv.y += logits[p] * vv.y;
            accv.z += logits[p] * vv.z;
            accv.w += logits[p] * vv.w;
        }

        float* op = out + ((size_t)b * C_ + c0) * HW_ + gy * W_ + gx;
        op[0]       = accv.x;
        op[HW_]     = accv.y;
        op[2 * HW_] = accv.z;
        op[3 * HW_] = accv.w;
    }
}

// ---------------------------------------------------------------------------
extern "C" void kernel_launch(void* const* d_in, const int* in_sizes, int n_in,
                              void* d_out, int out_size)
{
    const float* x  = (const float*)d_in[0];
    const float* Wq = (const float*)d_in[1];
    const float* bq = (const float*)d_in[2];
    const float* Wk = (const float*)d_in[3];
    const float* bk = (const float*)d_in[4];
    const float* Wv = (const float*)d_in[5];
    const float* bv = (const float*)d_in[6];
    float* out = (float*)d_out;

    dim3 ggrid(B_ * HW_ / 64, 3, 1);
    qkv_gemm<<<ggrid, 256>>>(x, Wq, bq, Wk, bk, Wv, bv);

    dim3 agrid(W_ / TW, H_ / TH, B_);
    local_attn<<<agrid, 128>>>(out);
}